// round 1
// baseline (speedup 1.0000x reference)
#include <cuda_runtime.h>
#include <math_constants.h>
#include <stdint.h>

// Problem constants (fixed by this dataset instance)
#define BATCH   2
#define CNUM    81          // num_classes incl. background
#define NCLS    (CNUM - 1)  // foreground classes
#define NP      CNUM        // num_pad = num_classes = 81
#define RMAX    1024        // padded ROI count (R = 1000)
#define NMS_THR 0.3f

// Scratch (device globals: no allocation allowed)
__device__ float g_dets[BATCH][NCLS][NP][5];
__device__ int   g_cnt[BATCH][NCLS];

// -------------------------------------------------------------------------
// Kernel 1: one CTA per (image b, class c).  Decode+clip boxes, threshold,
// stable-descending sort, greedy NMS over the valid prefix, store kept dets.
// -------------------------------------------------------------------------
__global__ void __launch_bounds__(256)
per_class_kernel(const float* __restrict__ cls_prob,   // (B,R,C)
                 const float* __restrict__ rois,       // (B,R,5)
                 const float* __restrict__ bbox_pred,  // (B,R,4C)
                 const float* __restrict__ im_info,    // (B,3)
                 const float* __restrict__ thr,        // (C,)
                 int R)
{
    const int c   = blockIdx.x + 1;   // class 1..80
    const int b   = blockIdx.y;
    const int tid = threadIdx.x;
    const int NT  = blockDim.x;

    __shared__ unsigned long long key[RMAX];             // (~score_key)<<32 | roi_idx
    __shared__ float bx1[RMAX], by1[RMAX], bx2[RMAX], by2[RMAX], bar[RMAX];
    __shared__ unsigned char keep[RMAX];
    __shared__ int vcnt;

    if (tid == 0) vcnt = 0;
    __syncthreads();

    const float h_im = im_info[b * 3 + 0];
    const float w_im = im_info[b * 3 + 1];
    const float th   = thr[c];

    // ---- decode + clip + key build ----
    for (int r = tid; r < RMAX; r += NT) {
        float skey = -CUDART_INF_F;
        if (r < R) {
            const float score = cls_prob[(size_t)(b * R + r) * CNUM + c];
            const bool  valid = score > th;

            const float* roi = rois + (size_t)(b * R + r) * 5;
            const float x1 = roi[1], y1 = roi[2], x2 = roi[3], y2 = roi[4];
            const float w  = x2 - x1 + 1.0f;
            const float h  = y2 - y1 + 1.0f;
            const float cx = x1 + 0.5f * w;
            const float cy = y1 + 0.5f * h;

            const float* dp = bbox_pred + ((size_t)(b * R + r) * CNUM + c) * 4;
            const float dx = dp[0] * 0.1f;
            const float dy = dp[1] * 0.1f;
            const float dw = dp[2] * 0.2f;
            const float dh = dp[3] * 0.2f;

            const float pcx = dx * w + cx;
            const float pcy = dy * h + cy;
            const float pw  = expf(dw) * w;
            const float ph  = expf(dh) * h;

            float nx1 = pcx - 0.5f * pw;
            float ny1 = pcy - 0.5f * ph;
            float nx2 = pcx + 0.5f * pw;
            float ny2 = pcy + 0.5f * ph;
            nx1 = fminf(fmaxf(nx1, 0.0f), w_im - 1.0f);
            nx2 = fminf(fmaxf(nx2, 0.0f), w_im - 1.0f);
            ny1 = fminf(fmaxf(ny1, 0.0f), h_im - 1.0f);
            ny2 = fminf(fmaxf(ny2, 0.0f), h_im - 1.0f);

            bx1[r] = nx1; by1[r] = ny1; bx2[r] = nx2; by2[r] = ny2;
            bar[r] = fmaxf(nx2 - nx1, 0.0f) * fmaxf(ny2 - ny1, 0.0f);

            if (valid) { skey = score; atomicAdd(&vcnt, 1); }
        }
        // monotone-ascending uint transform of float, then invert for descending
        uint32_t ub = __float_as_uint(skey);
        ub ^= (ub >> 31) ? 0xFFFFFFFFu : 0x80000000u;
        const uint32_t d = ~ub;
        key[r] = ((unsigned long long)d << 32) | (uint32_t)r;  // ties -> ascending idx (stable argsort)
    }
    __syncthreads();

    // ---- bitonic sort ascending on packed key (1024 elements) ----
    for (int k = 2; k <= RMAX; k <<= 1) {
        for (int j = k >> 1; j > 0; j >>= 1) {
            for (int i = tid; i < RMAX; i += NT) {
                const int ixj = i ^ j;
                if (ixj > i) {
                    const unsigned long long a = key[i];
                    const unsigned long long bb = key[ixj];
                    const bool up = ((i & k) == 0);
                    if (up ? (a > bb) : (a < bb)) { key[i] = bb; key[ixj] = a; }
                }
            }
            __syncthreads();
        }
    }

    const int V = vcnt;  // valid entries occupy sorted prefix [0, V)

    for (int i = tid; i < RMAX; i += NT) keep[i] = (i < V) ? 1 : 0;
    __syncthreads();

    // ---- greedy NMS over valid prefix ----
    for (int i = 0; i < V; ++i) {
        if (keep[i]) {
            const int   ri  = (int)(uint32_t)key[i];
            const float ax1 = bx1[ri], ay1 = by1[ri];
            const float ax2 = bx2[ri], ay2 = by2[ri];
            const float aa  = bar[ri];
            for (int j = i + 1 + tid; j < V; j += NT) {
                if (keep[j]) {
                    const int rj = (int)(uint32_t)key[j];
                    const float xx1 = fmaxf(ax1, bx1[rj]);
                    const float yy1 = fmaxf(ay1, by1[rj]);
                    const float xx2 = fminf(ax2, bx2[rj]);
                    const float yy2 = fminf(ay2, by2[rj]);
                    const float inter = fmaxf(xx2 - xx1, 0.0f) * fmaxf(yy2 - yy1, 0.0f);
                    const float iou = inter / (aa + bar[rj] - inter + 1e-9f);
                    if (iou > NMS_THR) keep[j] = 0;
                }
            }
        }
        __syncthreads();
    }

    // ---- compact kept dets (class-local, in sorted score order) ----
    if (tid == 0) {
        int k = 0;
        for (int i = 0; i < V; ++i) {
            if (keep[i]) {
                if (k < NP) {
                    const int ri = (int)(uint32_t)key[i];
                    g_dets[b][c - 1][k][0] = bx1[ri];
                    g_dets[b][c - 1][k][1] = by1[ri];
                    g_dets[b][c - 1][k][2] = bx2[ri];
                    g_dets[b][c - 1][k][3] = by2[ri];
                    g_dets[b][c - 1][k][4] = (float)c;
                }
                ++k;
            }
        }
        g_cnt[b][c - 1] = k;
    }
}

// -------------------------------------------------------------------------
// Kernel 2: zero output, then class-major compaction into the first NP rows
// per image, plus n = min(total_kept, NP).
// -------------------------------------------------------------------------
__global__ void combine_kernel(float* __restrict__ out, int out_size)
{
    const int b = blockIdx.x;
    float* gout = out + (size_t)b * NP * 5;

    for (int i = threadIdx.x; i < NP * 5; i += blockDim.x) gout[i] = 0.0f;
    __syncthreads();

    if (threadIdx.x == 0) {
        int k = 0, total = 0;
        for (int c = 0; c < NCLS; ++c) {
            const int cnt  = g_cnt[b][c];
            total += cnt;
            const int take = cnt < NP ? cnt : NP;  // only first NP stored per class
            for (int t = 0; t < take && k < NP; ++t, ++k) {
                gout[k * 5 + 0] = g_dets[b][c][t][0];
                gout[k * 5 + 1] = g_dets[b][c][t][1];
                gout[k * 5 + 2] = g_dets[b][c][t][2];
                gout[k * 5 + 3] = g_dets[b][c][t][3];
                gout[k * 5 + 4] = g_dets[b][c][t][4];
            }
        }
        const int n = total < NP ? total : NP;
        if (out_size >= BATCH * NP * 5 + BATCH)
            out[BATCH * NP * 5 + b] = (float)n;
    }
}

// Safety net: zero any remaining poisoned output elements beyond what the
// combine kernel writes.
__global__ void zero_tail_kernel(float* __restrict__ out, int out_size)
{
    const int base = BATCH * NP * 5 + BATCH;
    for (int i = base + blockIdx.x * blockDim.x + threadIdx.x; i < out_size;
         i += gridDim.x * blockDim.x)
        out[i] = 0.0f;
}

extern "C" void kernel_launch(void* const* d_in, const int* in_sizes, int n_in,
                              void* d_out, int out_size)
{
    const float* cls_prob  = (const float*)d_in[0];  // (B,R,C)
    const float* rois      = (const float*)d_in[1];  // (B,R,5)
    const float* bbox_pred = (const float*)d_in[2];  // (B,R,4C)
    const float* im_info   = (const float*)d_in[3];  // (B,3)
    const float* thr       = (const float*)d_in[4];  // (C,)
    float* out = (float*)d_out;

    const int R = in_sizes[0] / (BATCH * CNUM);      // 1000

    dim3 grid(NCLS, BATCH);
    per_class_kernel<<<grid, 256>>>(cls_prob, rois, bbox_pred, im_info, thr, R);
    combine_kernel<<<BATCH, 128>>>(out, out_size);
    if (out_size > BATCH * NP * 5 + BATCH)
        zero_tail_kernel<<<1, 256>>>(out, out_size);
}

// round 2
// speedup vs baseline: 1.7901x; 1.7901x over previous
#include <cuda_runtime.h>
#include <math_constants.h>
#include <stdint.h>

// Problem constants (fixed by this dataset instance)
#define BATCH   2
#define CNUM    81          // num_classes incl. background
#define NCLS    (CNUM - 1)  // foreground classes
#define NP      CNUM        // num_pad = num_classes = 81
#define RMAX    1024        // padded ROI count (R = 1000)
#define VMAX    256         // fast-path cap for matrix NMS
#define NMS_THR 0.3f

// Scratch (device globals: no allocation allowed)
__device__ float g_dets[BATCH][NCLS][NP][5];
__device__ int   g_cnt[BATCH][NCLS];

// -------------------------------------------------------------------------
// Kernel 1: one CTA per (image b, class c).
//   decode+clip -> threshold+compact -> small bitonic sort -> matrix NMS
// -------------------------------------------------------------------------
__global__ void __launch_bounds__(256)
per_class_kernel(const float* __restrict__ cls_prob,   // (B,R,C)
                 const float* __restrict__ rois,       // (B,R,5)
                 const float* __restrict__ bbox_pred,  // (B,R,4C)
                 const float* __restrict__ im_info,    // (B,3)
                 const float* __restrict__ thr,        // (C,)
                 int R)
{
    const int c   = blockIdx.x + 1;   // class 1..80
    const int b   = blockIdx.y;
    const int tid = threadIdx.x;
    const int NT  = blockDim.x;

    __shared__ unsigned long long key[RMAX];           // (inv_score)<<32 | roi_idx
    __shared__ float bx1[RMAX], by1[RMAX], bx2[RMAX], by2[RMAX], bar[RMAX];
    __shared__ unsigned long long sup[VMAX][4];        // suppression bitmask rows
    __shared__ unsigned char keep[RMAX];               // fallback path only
    __shared__ int vcnt;
    __shared__ unsigned long long keptw[16];           // final kept bits (V<=1024)

    if (tid == 0) vcnt = 0;
    __syncthreads();

    const float h_im = im_info[b * 3 + 0];
    const float w_im = im_info[b * 3 + 1];
    const float th   = thr[c];

    // ---- decode + clip; compact valid keys (order-free: sort key is total) ----
    for (int r = tid; r < R; r += NT) {
        const float score = cls_prob[(size_t)(b * R + r) * CNUM + c];

        const float* roi = rois + (size_t)(b * R + r) * 5;
        const float x1 = roi[1], y1 = roi[2], x2 = roi[3], y2 = roi[4];
        const float w  = x2 - x1 + 1.0f;
        const float h  = y2 - y1 + 1.0f;
        const float cx = x1 + 0.5f * w;
        const float cy = y1 + 0.5f * h;

        const float4 d4 = *(const float4*)(bbox_pred + ((size_t)(b * R + r) * CNUM + c) * 4);
        const float dx = d4.x * 0.1f;
        const float dy = d4.y * 0.1f;
        const float dw = d4.z * 0.2f;
        const float dh = d4.w * 0.2f;

        const float pcx = dx * w + cx;
        const float pcy = dy * h + cy;
        const float pw  = expf(dw) * w;
        const float ph  = expf(dh) * h;

        float nx1 = pcx - 0.5f * pw;
        float ny1 = pcy - 0.5f * ph;
        float nx2 = pcx + 0.5f * pw;
        float ny2 = pcy + 0.5f * ph;
        nx1 = fminf(fmaxf(nx1, 0.0f), w_im - 1.0f);
        nx2 = fminf(fmaxf(nx2, 0.0f), w_im - 1.0f);
        ny1 = fminf(fmaxf(ny1, 0.0f), h_im - 1.0f);
        ny2 = fminf(fmaxf(ny2, 0.0f), h_im - 1.0f);

        bx1[r] = nx1; by1[r] = ny1; bx2[r] = nx2; by2[r] = ny2;
        bar[r] = fmaxf(nx2 - nx1, 0.0f) * fmaxf(ny2 - ny1, 0.0f);

        if (score > th) {
            // monotone uint transform (score > 0 here), inverted for descending
            uint32_t ub = __float_as_uint(score) ^ 0x80000000u;
            const int pos = atomicAdd(&vcnt, 1);
            key[pos] = ((unsigned long long)(~ub) << 32) | (uint32_t)r;
        }
    }
    __syncthreads();

    const int V = vcnt;

    // ---- pad to power of two and bitonic sort ascending ----
    int S = 32;
    while (S < V) S <<= 1;          // S <= 1024
    for (int i = V + tid; i < S; i += NT) key[i] = ~0ULL;
    __syncthreads();

    for (int k = 2; k <= S; k <<= 1) {
        for (int j = k >> 1; j > 0; j >>= 1) {
            for (int i = tid; i < S; i += NT) {
                const int ixj = i ^ j;
                if (ixj > i) {
                    const unsigned long long a = key[i];
                    const unsigned long long bb = key[ixj];
                    const bool up = ((i & k) == 0);
                    if (up ? (a > bb) : (a < bb)) { key[i] = bb; key[ixj] = a; }
                }
            }
            __syncthreads();
        }
    }

    if (V <= VMAX) {
        // ---- matrix NMS: each thread builds one 64-bit mask word, no atomics ----
        const int W = (V + 63) >> 6;             // words per row, 0..4
        for (int t = tid; t < V * W; t += NT) {
            const int i = t / W;
            const int w = t - i * W;
            const int ri  = (int)(uint32_t)key[i];
            const float ax1 = bx1[ri], ay1 = by1[ri];
            const float ax2 = bx2[ri], ay2 = by2[ri];
            const float aa  = bar[ri];
            unsigned long long bits = 0ULL;
            const int j0 = max(i + 1, w << 6);
            const int j1 = min(V, (w + 1) << 6);
            for (int j = j0; j < j1; ++j) {
                const int rj = (int)(uint32_t)key[j];
                const float xx1 = fmaxf(ax1, bx1[rj]);
                const float yy1 = fmaxf(ay1, by1[rj]);
                const float xx2 = fminf(ax2, bx2[rj]);
                const float yy2 = fminf(ay2, by2[rj]);
                const float inter = fmaxf(xx2 - xx1, 0.0f) * fmaxf(yy2 - yy1, 0.0f);
                const float iou = inter / (aa + bar[rj] - inter + 1e-9f);
                if (iou > NMS_THR) bits |= 1ULL << (j & 63);
            }
            sup[i][w] = bits;
        }
        __syncthreads();

        // ---- single-thread greedy scan over bitmasks + compaction ----
        if (tid == 0) {
            unsigned long long kw[4];
            const int W2 = (V + 63) >> 6;
            for (int w = 0; w < 4; ++w) kw[w] = 0ULL;
            for (int i = 0; i < V; ++i) kw[i >> 6] |= 1ULL << (i & 63);
            int k = 0;
            for (int i = 0; i < V; ++i) {
                if ((kw[i >> 6] >> (i & 63)) & 1ULL) {
                    for (int w = 0; w < W2; ++w) kw[w] &= ~sup[i][w];
                    if (k < NP) {
                        const int ri = (int)(uint32_t)key[i];
                        g_dets[b][c - 1][k][0] = bx1[ri];
                        g_dets[b][c - 1][k][1] = by1[ri];
                        g_dets[b][c - 1][k][2] = bx2[ri];
                        g_dets[b][c - 1][k][3] = by2[ri];
                        g_dets[b][c - 1][k][4] = (float)c;
                    }
                    ++k;
                }
            }
            g_cnt[b][c - 1] = k;
        }
    } else {
        // ---- fallback: barrier-loop greedy NMS (rarely taken) ----
        for (int i = tid; i < V; i += NT) keep[i] = 1;
        __syncthreads();
        for (int i = 0; i < V; ++i) {
            if (keep[i]) {
                const int   ri  = (int)(uint32_t)key[i];
                const float ax1 = bx1[ri], ay1 = by1[ri];
                const float ax2 = bx2[ri], ay2 = by2[ri];
                const float aa  = bar[ri];
                for (int j = i + 1 + tid; j < V; j += NT) {
                    if (keep[j]) {
                        const int rj = (int)(uint32_t)key[j];
                        const float xx1 = fmaxf(ax1, bx1[rj]);
                        const float yy1 = fmaxf(ay1, by1[rj]);
                        const float xx2 = fminf(ax2, bx2[rj]);
                        const float yy2 = fminf(ay2, by2[rj]);
                        const float inter = fmaxf(xx2 - xx1, 0.0f) * fmaxf(yy2 - yy1, 0.0f);
                        const float iou = inter / (aa + bar[rj] - inter + 1e-9f);
                        if (iou > NMS_THR) keep[j] = 0;
                    }
                }
            }
            __syncthreads();
        }
        if (tid == 0) {
            int k = 0;
            for (int i = 0; i < V; ++i) {
                if (keep[i]) {
                    if (k < NP) {
                        const int ri = (int)(uint32_t)key[i];
                        g_dets[b][c - 1][k][0] = bx1[ri];
                        g_dets[b][c - 1][k][1] = by1[ri];
                        g_dets[b][c - 1][k][2] = bx2[ri];
                        g_dets[b][c - 1][k][3] = by2[ri];
                        g_dets[b][c - 1][k][4] = (float)c;
                    }
                    ++k;
                }
            }
            g_cnt[b][c - 1] = k;
        }
    }
    (void)keptw;
}

// -------------------------------------------------------------------------
// Kernel 2: parallel class-major compaction. One CTA per image.
// -------------------------------------------------------------------------
__global__ void __launch_bounds__(128)
combine_kernel(float* __restrict__ out, int out_size)
{
    const int b = blockIdx.x;
    const int tid = threadIdx.x;
    __shared__ int p[NCLS + 1];

    if (tid == 0) {
        int acc = 0;
        for (int c = 0; c < NCLS; ++c) { p[c] = acc; acc += g_cnt[b][c]; }
        p[NCLS] = acc;
    }

    float* gout = out + (size_t)b * NP * 5;
    for (int i = tid; i < NP * 5; i += blockDim.x) gout[i] = 0.0f;
    __syncthreads();

    const int total = p[NCLS];
    const int n = total < NP ? total : NP;

    const int k = tid;
    if (k < n) {
        int c = 0;
        while (p[c + 1] <= k) ++c;          // k < total ensures termination
        const int t = k - p[c];
        #pragma unroll
        for (int q = 0; q < 5; ++q)
            gout[k * 5 + q] = g_dets[b][c][t][q];
    }

    if (tid == 0 && out_size >= BATCH * NP * 5 + BATCH)
        out[BATCH * NP * 5 + b] = (float)n;

    // tail zero (anything beyond gt + n), block 0 only
    if (b == 0) {
        const int base = BATCH * NP * 5 + BATCH;
        for (int i = base + tid; i < out_size; i += blockDim.x) out[i] = 0.0f;
    }
}

extern "C" void kernel_launch(void* const* d_in, const int* in_sizes, int n_in,
                              void* d_out, int out_size)
{
    const float* cls_prob  = (const float*)d_in[0];  // (B,R,C)
    const float* rois      = (const float*)d_in[1];  // (B,R,5)
    const float* bbox_pred = (const float*)d_in[2];  // (B,R,4C)
    const float* im_info   = (const float*)d_in[3];  // (B,3)
    const float* thr       = (const float*)d_in[4];  // (C,)
    float* out = (float*)d_out;

    const int R = in_sizes[0] / (BATCH * CNUM);      // 1000

    dim3 grid(NCLS, BATCH);
    per_class_kernel<<<grid, 256>>>(cls_prob, rois, bbox_pred, im_info, thr, R);
    combine_kernel<<<BATCH, 128>>>(out, out_size);
}

// round 3
// speedup vs baseline: 1.7915x; 1.0008x over previous
#include <cuda_runtime.h>
#include <math_constants.h>
#include <stdint.h>

// Problem constants (fixed by this dataset instance)
#define BATCH   2
#define CNUM    81          // num_classes incl. background
#define NCLS    (CNUM - 1)  // foreground classes
#define NP      CNUM        // num_pad = num_classes = 81
#define RMAX    1024        // padded ROI count (R = 1000)
#define VMAX    256         // fast-path cap for matrix NMS
#define NMS_THR 0.3f
#define NBLK    (NCLS * BATCH)   // 160

// Scratch (device globals: no allocation allowed)
__device__ float g_dets[BATCH][NCLS][NP][5];
__device__ int   g_cnt[BATCH][NCLS];
__device__ unsigned int g_done = 0;     // self-resetting completion counter

// -------------------------------------------------------------------------
// Fused kernel: one CTA per (image b, class c).
//   score scan -> compact valid -> small bitonic sort -> lazy decode ->
//   matrix NMS -> per-class store; last CTA combines into d_out.
// -------------------------------------------------------------------------
__global__ void __launch_bounds__(256)
fused_kernel(const float* __restrict__ cls_prob,   // (B,R,C)
             const float* __restrict__ rois,       // (B,R,5)
             const float* __restrict__ bbox_pred,  // (B,R,4C)
             const float* __restrict__ im_info,    // (B,3)
             const float* __restrict__ thr,        // (C,)
             float* __restrict__ out, int out_size,
             int R)
{
    const int c   = blockIdx.x + 1;   // class 1..80
    const int b   = blockIdx.y;
    const int tid = threadIdx.x;
    const int NT  = blockDim.x;

    __shared__ unsigned long long key[RMAX];       // (inv_score)<<32 | roi_idx
    __shared__ float vx1[RMAX], vy1[RMAX], vx2[RMAX], vy2[RMAX], var_[RMAX];
    __shared__ unsigned long long sup[VMAX][4];    // suppression bitmask rows
    __shared__ unsigned char keep[RMAX];           // fallback path only
    __shared__ int vcnt;

    if (tid == 0) vcnt = 0;
    __syncthreads();

    const float h_im = im_info[b * 3 + 0];
    const float w_im = im_info[b * 3 + 1];
    const float th   = thr[c];

    // ---- pass 1: score scan + compaction of valid roi indices ----
    for (int r = tid; r < R; r += NT) {
        const float score = cls_prob[(size_t)(b * R + r) * CNUM + c];
        if (score > th) {
            // monotone uint transform (score > 0 here), inverted for descending
            const uint32_t ub = __float_as_uint(score) ^ 0x80000000u;
            const int pos = atomicAdd(&vcnt, 1);
            key[pos] = ((unsigned long long)(~ub) << 32) | (uint32_t)r;
        }
    }
    __syncthreads();

    const int V = vcnt;

    // ---- pad to power of two and bitonic sort ascending on full key ----
    int S = 32;
    while (S < V) S <<= 1;          // S <= 1024
    for (int i = V + tid; i < S; i += NT) key[i] = ~0ULL;
    __syncthreads();

    for (int k = 2; k <= S; k <<= 1) {
        for (int j = k >> 1; j > 0; j >>= 1) {
            for (int i = tid; i < S; i += NT) {
                const int ixj = i ^ j;
                if (ixj > i) {
                    const unsigned long long a = key[i];
                    const unsigned long long bb = key[ixj];
                    const bool up = ((i & k) == 0);
                    if (up ? (a > bb) : (a < bb)) { key[i] = bb; key[ixj] = a; }
                }
            }
            __syncthreads();
        }
    }

    // ---- lazy decode: only the V survivors, stored by sorted rank ----
    for (int i = tid; i < V; i += NT) {
        const int r = (int)(uint32_t)key[i];

        const float* roi = rois + (size_t)(b * R + r) * 5;
        const float x1 = roi[1], y1 = roi[2], x2 = roi[3], y2 = roi[4];
        const float w  = x2 - x1 + 1.0f;
        const float h  = y2 - y1 + 1.0f;
        const float cx = x1 + 0.5f * w;
        const float cy = y1 + 0.5f * h;

        const float4 d4 = *(const float4*)(bbox_pred + ((size_t)(b * R + r) * CNUM + c) * 4);
        const float dx = d4.x * 0.1f;
        const float dy = d4.y * 0.1f;
        const float dw = d4.z * 0.2f;
        const float dh = d4.w * 0.2f;

        const float pcx = dx * w + cx;
        const float pcy = dy * h + cy;
        const float pw  = expf(dw) * w;
        const float ph  = expf(dh) * h;

        float nx1 = pcx - 0.5f * pw;
        float ny1 = pcy - 0.5f * ph;
        float nx2 = pcx + 0.5f * pw;
        float ny2 = pcy + 0.5f * ph;
        nx1 = fminf(fmaxf(nx1, 0.0f), w_im - 1.0f);
        nx2 = fminf(fmaxf(nx2, 0.0f), w_im - 1.0f);
        ny1 = fminf(fmaxf(ny1, 0.0f), h_im - 1.0f);
        ny2 = fminf(fmaxf(ny2, 0.0f), h_im - 1.0f);

        vx1[i] = nx1; vy1[i] = ny1; vx2[i] = nx2; vy2[i] = ny2;
        var_[i] = fmaxf(nx2 - nx1, 0.0f) * fmaxf(ny2 - ny1, 0.0f);
    }
    __syncthreads();

    if (V <= VMAX) {
        // ---- matrix NMS: each thread builds one 64-bit mask word ----
        const int W = (V + 63) >> 6;
        for (int t = tid; t < V * W; t += NT) {
            const int i = t / W;
            const int w = t - i * W;
            const float ax1 = vx1[i], ay1 = vy1[i];
            const float ax2 = vx2[i], ay2 = vy2[i];
            const float aa  = var_[i];
            unsigned long long bits = 0ULL;
            const int j0 = max(i + 1, w << 6);
            const int j1 = min(V, (w + 1) << 6);
            for (int j = j0; j < j1; ++j) {
                const float xx1 = fmaxf(ax1, vx1[j]);
                const float yy1 = fmaxf(ay1, vy1[j]);
                const float xx2 = fminf(ax2, vx2[j]);
                const float yy2 = fminf(ay2, vy2[j]);
                const float inter = fmaxf(xx2 - xx1, 0.0f) * fmaxf(yy2 - yy1, 0.0f);
                const float iou = inter / (aa + var_[j] - inter + 1e-9f);
                if (iou > NMS_THR) bits |= 1ULL << (j & 63);
            }
            sup[i][w] = bits;
        }
        __syncthreads();

        // ---- single-thread greedy scan over bitmasks + per-class store ----
        if (tid == 0) {
            unsigned long long kw[4] = {0, 0, 0, 0};
            const int W2 = (V + 63) >> 6;
            for (int i = 0; i < V; ++i) kw[i >> 6] |= 1ULL << (i & 63);
            int k = 0;
            for (int i = 0; i < V; ++i) {
                if ((kw[i >> 6] >> (i & 63)) & 1ULL) {
                    for (int w = 0; w < W2; ++w) kw[w] &= ~sup[i][w];
                    if (k < NP) {
                        g_dets[b][c - 1][k][0] = vx1[i];
                        g_dets[b][c - 1][k][1] = vy1[i];
                        g_dets[b][c - 1][k][2] = vx2[i];
                        g_dets[b][c - 1][k][3] = vy2[i];
                        g_dets[b][c - 1][k][4] = (float)c;
                    }
                    ++k;
                }
            }
            g_cnt[b][c - 1] = k;
        }
    } else {
        // ---- fallback: barrier-loop greedy NMS (rarely taken) ----
        for (int i = tid; i < V; i += NT) keep[i] = 1;
        __syncthreads();
        for (int i = 0; i < V; ++i) {
            if (keep[i]) {
                const float ax1 = vx1[i], ay1 = vy1[i];
                const float ax2 = vx2[i], ay2 = vy2[i];
                const float aa  = var_[i];
                for (int j = i + 1 + tid; j < V; j += NT) {
                    if (keep[j]) {
                        const float xx1 = fmaxf(ax1, vx1[j]);
                        const float yy1 = fmaxf(ay1, vy1[j]);
                        const float xx2 = fminf(ax2, vx2[j]);
                        const float yy2 = fminf(ay2, vy2[j]);
                        const float inter = fmaxf(xx2 - xx1, 0.0f) * fmaxf(yy2 - yy1, 0.0f);
                        const float iou = inter / (aa + var_[j] - inter + 1e-9f);
                        if (iou > NMS_THR) keep[j] = 0;
                    }
                }
            }
            __syncthreads();
        }
        if (tid == 0) {
            int k = 0;
            for (int i = 0; i < V; ++i) {
                if (keep[i]) {
                    if (k < NP) {
                        g_dets[b][c - 1][k][0] = vx1[i];
                        g_dets[b][c - 1][k][1] = vy1[i];
                        g_dets[b][c - 1][k][2] = vx2[i];
                        g_dets[b][c - 1][k][3] = vy2[i];
                        g_dets[b][c - 1][k][4] = (float)c;
                    }
                    ++k;
                }
            }
            g_cnt[b][c - 1] = k;
        }
    }

    // ======== last-block-done combine ========
    __threadfence();
    __syncthreads();

    __shared__ unsigned int is_last;
    if (tid == 0) is_last = (atomicAdd(&g_done, 1u) == NBLK - 1u) ? 1u : 0u;
    __syncthreads();
    if (!is_last) return;

    // Reuse shared memory for prefix sums over per-class counts.
    __shared__ int cnts[BATCH][NCLS];
    __shared__ int pfx[BATCH][NCLS + 1];

    for (int t = tid; t < BATCH * NCLS; t += NT)
        cnts[t / NCLS][t % NCLS] = g_cnt[t / NCLS][t % NCLS];
    __syncthreads();

    if (tid < BATCH) {
        int acc = 0;
        for (int cc = 0; cc < NCLS; ++cc) { pfx[tid][cc] = acc; acc += cnts[tid][cc]; }
        pfx[tid][NCLS] = acc;
    }
    __syncthreads();

    // zero gt region
    for (int i = tid; i < BATCH * NP * 5; i += NT) out[i] = 0.0f;
    __syncthreads();

    // one thread per (image, slot)
    for (int t = tid; t < BATCH * NP; t += NT) {
        const int bb = t / NP;
        const int k  = t - bb * NP;
        const int total = pfx[bb][NCLS];
        const int n = total < NP ? total : NP;
        if (k < n) {
            int cc = 0;
            while (pfx[bb][cc + 1] <= k) ++cc;
            const int tt = k - pfx[bb][cc];
            float* gout = out + (size_t)bb * NP * 5 + (size_t)k * 5;
            #pragma unroll
            for (int q = 0; q < 5; ++q) gout[q] = g_dets[bb][cc][tt][q];
        }
        if (k == 0 && out_size >= BATCH * NP * 5 + BATCH)
            out[BATCH * NP * 5 + bb] = (float)n;
    }

    // zero any tail beyond gt + n
    const int base = BATCH * NP * 5 + BATCH;
    for (int i = base + tid; i < out_size; i += NT) out[i] = 0.0f;

    // reset counter for next graph replay (deterministic across launches)
    __syncthreads();
    if (tid == 0) g_done = 0;
}

extern "C" void kernel_launch(void* const* d_in, const int* in_sizes, int n_in,
                              void* d_out, int out_size)
{
    const float* cls_prob  = (const float*)d_in[0];  // (B,R,C)
    const float* rois      = (const float*)d_in[1];  // (B,R,5)
    const float* bbox_pred = (const float*)d_in[2];  // (B,R,4C)
    const float* im_info   = (const float*)d_in[3];  // (B,3)
    const float* thr       = (const float*)d_in[4];  // (C,)
    float* out = (float*)d_out;

    const int R = in_sizes[0] / (BATCH * CNUM);      // 1000

    dim3 grid(NCLS, BATCH);
    fused_kernel<<<grid, 256>>>(cls_prob, rois, bbox_pred, im_info, thr,
                                out, out_size, R);
}

// round 4
// speedup vs baseline: 1.9863x; 1.1087x over previous
#include <cuda_runtime.h>
#include <math_constants.h>
#include <stdint.h>

// Problem constants (fixed by this dataset instance)
#define BATCH   2
#define CNUM    81          // num_classes incl. background
#define NCLS    (CNUM - 1)  // foreground classes
#define NP      CNUM        // num_pad = num_classes = 81
#define RMAX    1024        // padded ROI count (R = 1000)
#define VMAX    256         // fast-path cap for matrix NMS
#define NMS_THR 0.3f
#define NBLK    (NCLS * BATCH)   // 160

// Scratch (device globals: no allocation allowed)
__device__ float g_dets[BATCH][NCLS][NP][5];
__device__ int   g_cnt[BATCH][NCLS];
__device__ unsigned int g_done = 0;     // self-resetting completion counter

// -------------------------------------------------------------------------
// Fused kernel: one CTA per (image b, class c).
//   score scan -> compact -> O(V^2) rank sort (2 barriers) -> lazy decode ->
//   matrix NMS -> per-class store; last CTA combines into d_out.
// -------------------------------------------------------------------------
__global__ void __launch_bounds__(256)
fused_kernel(const float* __restrict__ cls_prob,   // (B,R,C)
             const float* __restrict__ rois,       // (B,R,5)
             const float* __restrict__ bbox_pred,  // (B,R,4C)
             const float* __restrict__ im_info,    // (B,3)
             const float* __restrict__ thr,        // (C,)
             float* __restrict__ out, int out_size,
             int R)
{
    const int c   = blockIdx.x + 1;   // class 1..80
    const int b   = blockIdx.y;
    const int tid = threadIdx.x;
    const int NT  = blockDim.x;

    __shared__ unsigned long long ukey[RMAX];      // unsorted (inv_score)<<32 | idx
    __shared__ unsigned long long skey[RMAX];      // rank-ordered
    __shared__ float vx1[RMAX], vy1[RMAX], vx2[RMAX], vy2[RMAX], var_[RMAX];
    __shared__ unsigned long long sup[VMAX][4];    // suppression bitmask rows
    __shared__ unsigned char keep[RMAX];           // fallback path only
    __shared__ int vcnt;

    if (tid == 0) vcnt = 0;
    __syncthreads();

    const float h_im = im_info[b * 3 + 0];
    const float w_im = im_info[b * 3 + 1];
    const float th   = thr[c];

    // ---- pass 1: score scan + compaction of valid roi indices ----
    for (int r = tid; r < R; r += NT) {
        const float score = cls_prob[(size_t)(b * R + r) * CNUM + c];
        if (score > th) {
            // monotone uint transform (score > 0 here), inverted for descending
            const uint32_t ub = __float_as_uint(score) ^ 0x80000000u;
            const int pos = atomicAdd(&vcnt, 1);
            ukey[pos] = ((unsigned long long)(~ub) << 32) | (uint32_t)r;
        }
    }
    __syncthreads();

    const int V = vcnt;

    // ---- rank sort: keys are distinct, rank = #{smaller keys}. 2 barriers. ----
    for (int i = tid; i < V; i += NT) {
        const unsigned long long ki = ukey[i];
        int rank = 0;
        for (int j = 0; j < V; ++j)
            rank += (ukey[j] < ki);
        skey[rank] = ki;
    }
    __syncthreads();

    // ---- lazy decode: only the V survivors, stored by sorted rank ----
    for (int i = tid; i < V; i += NT) {
        const int r = (int)(uint32_t)skey[i];

        const float* roi = rois + (size_t)(b * R + r) * 5;
        const float x1 = roi[1], y1 = roi[2], x2 = roi[3], y2 = roi[4];
        const float w  = x2 - x1 + 1.0f;
        const float h  = y2 - y1 + 1.0f;
        const float cx = x1 + 0.5f * w;
        const float cy = y1 + 0.5f * h;

        const float4 d4 = *(const float4*)(bbox_pred + ((size_t)(b * R + r) * CNUM + c) * 4);
        const float dx = d4.x * 0.1f;
        const float dy = d4.y * 0.1f;
        const float dw = d4.z * 0.2f;
        const float dh = d4.w * 0.2f;

        const float pcx = dx * w + cx;
        const float pcy = dy * h + cy;
        const float pw  = expf(dw) * w;
        const float ph  = expf(dh) * h;

        float nx1 = pcx - 0.5f * pw;
        float ny1 = pcy - 0.5f * ph;
        float nx2 = pcx + 0.5f * pw;
        float ny2 = pcy + 0.5f * ph;
        nx1 = fminf(fmaxf(nx1, 0.0f), w_im - 1.0f);
        nx2 = fminf(fmaxf(nx2, 0.0f), w_im - 1.0f);
        ny1 = fminf(fmaxf(ny1, 0.0f), h_im - 1.0f);
        ny2 = fminf(fmaxf(ny2, 0.0f), h_im - 1.0f);

        vx1[i] = nx1; vy1[i] = ny1; vx2[i] = nx2; vy2[i] = ny2;
        var_[i] = fmaxf(nx2 - nx1, 0.0f) * fmaxf(ny2 - ny1, 0.0f);
    }
    __syncthreads();

    if (V <= VMAX) {
        // ---- matrix NMS: each thread builds one 64-bit mask word ----
        const int W = (V + 63) >> 6;
        for (int t = tid; t < V * W; t += NT) {
            const int i = t / W;
            const int w = t - i * W;
            const float ax1 = vx1[i], ay1 = vy1[i];
            const float ax2 = vx2[i], ay2 = vy2[i];
            const float aa  = var_[i];
            unsigned long long bits = 0ULL;
            const int j0 = max(i + 1, w << 6);
            const int j1 = min(V, (w + 1) << 6);
            for (int j = j0; j < j1; ++j) {
                const float xx1 = fmaxf(ax1, vx1[j]);
                const float yy1 = fmaxf(ay1, vy1[j]);
                const float xx2 = fminf(ax2, vx2[j]);
                const float yy2 = fminf(ay2, vy2[j]);
                const float inter = fmaxf(xx2 - xx1, 0.0f) * fmaxf(yy2 - yy1, 0.0f);
                const float iou = inter / (aa + var_[j] - inter + 1e-9f);
                if (iou > NMS_THR) bits |= 1ULL << (j & 63);
            }
            sup[i][w] = bits;
        }
        __syncthreads();

        // ---- single-thread greedy scan over bitmasks + per-class store ----
        if (tid == 0) {
            unsigned long long kw[4] = {0, 0, 0, 0};
            const int W2 = (V + 63) >> 6;
            for (int i = 0; i < V; ++i) kw[i >> 6] |= 1ULL << (i & 63);
            int k = 0;
            for (int i = 0; i < V; ++i) {
                if ((kw[i >> 6] >> (i & 63)) & 1ULL) {
                    for (int w = 0; w < W2; ++w) kw[w] &= ~sup[i][w];
                    if (k < NP) {
                        g_dets[b][c - 1][k][0] = vx1[i];
                        g_dets[b][c - 1][k][1] = vy1[i];
                        g_dets[b][c - 1][k][2] = vx2[i];
                        g_dets[b][c - 1][k][3] = vy2[i];
                        g_dets[b][c - 1][k][4] = (float)c;
                    }
                    ++k;
                }
            }
            g_cnt[b][c - 1] = k;
        }
    } else {
        // ---- fallback: barrier-loop greedy NMS (rarely taken) ----
        for (int i = tid; i < V; i += NT) keep[i] = 1;
        __syncthreads();
        for (int i = 0; i < V; ++i) {
            if (keep[i]) {
                const float ax1 = vx1[i], ay1 = vy1[i];
                const float ax2 = vx2[i], ay2 = vy2[i];
                const float aa  = var_[i];
                for (int j = i + 1 + tid; j < V; j += NT) {
                    if (keep[j]) {
                        const float xx1 = fmaxf(ax1, vx1[j]);
                        const float yy1 = fmaxf(ay1, vy1[j]);
                        const float xx2 = fminf(ax2, vx2[j]);
                        const float yy2 = fminf(ay2, vy2[j]);
                        const float inter = fmaxf(xx2 - xx1, 0.0f) * fmaxf(yy2 - yy1, 0.0f);
                        const float iou = inter / (aa + var_[j] - inter + 1e-9f);
                        if (iou > NMS_THR) keep[j] = 0;
                    }
                }
            }
            __syncthreads();
        }
        if (tid == 0) {
            int k = 0;
            for (int i = 0; i < V; ++i) {
                if (keep[i]) {
                    if (k < NP) {
                        g_dets[b][c - 1][k][0] = vx1[i];
                        g_dets[b][c - 1][k][1] = vy1[i];
                        g_dets[b][c - 1][k][2] = vx2[i];
                        g_dets[b][c - 1][k][3] = vy2[i];
                        g_dets[b][c - 1][k][4] = (float)c;
                    }
                    ++k;
                }
            }
            g_cnt[b][c - 1] = k;
        }
    }

    // ======== last-block-done combine ========
    __threadfence();
    __syncthreads();

    __shared__ unsigned int is_last;
    if (tid == 0) is_last = (atomicAdd(&g_done, 1u) == NBLK - 1u) ? 1u : 0u;
    __syncthreads();
    if (!is_last) return;

    __shared__ int cnts[BATCH][NCLS];
    __shared__ int pfx[BATCH][NCLS + 1];

    for (int t = tid; t < BATCH * NCLS; t += NT)
        cnts[t / NCLS][t % NCLS] = g_cnt[t / NCLS][t % NCLS];
    __syncthreads();

    if (tid < BATCH) {
        int acc = 0;
        for (int cc = 0; cc < NCLS; ++cc) { pfx[tid][cc] = acc; acc += cnts[tid][cc]; }
        pfx[tid][NCLS] = acc;
    }
    __syncthreads();

    // zero gt region
    for (int i = tid; i < BATCH * NP * 5; i += NT) out[i] = 0.0f;
    __syncthreads();

    // one thread per (image, slot)
    for (int t = tid; t < BATCH * NP; t += NT) {
        const int bb = t / NP;
        const int k  = t - bb * NP;
        const int total = pfx[bb][NCLS];
        const int n = total < NP ? total : NP;
        if (k < n) {
            int cc = 0;
            while (pfx[bb][cc + 1] <= k) ++cc;
            const int tt = k - pfx[bb][cc];
            float* gout = out + (size_t)bb * NP * 5 + (size_t)k * 5;
            #pragma unroll
            for (int q = 0; q < 5; ++q) gout[q] = g_dets[bb][cc][tt][q];
        }
        if (k == 0 && out_size >= BATCH * NP * 5 + BATCH)
            out[BATCH * NP * 5 + bb] = (float)n;
    }

    // zero any tail beyond gt + n
    const int base = BATCH * NP * 5 + BATCH;
    for (int i = base + tid; i < out_size; i += NT) out[i] = 0.0f;

    // reset counter for next graph replay (deterministic across launches)
    __syncthreads();
    if (tid == 0) g_done = 0;
}

extern "C" void kernel_launch(void* const* d_in, const int* in_sizes, int n_in,
                              void* d_out, int out_size)
{
    const float* cls_prob  = (const float*)d_in[0];  // (B,R,C)
    const float* rois      = (const float*)d_in[1];  // (B,R,5)
    const float* bbox_pred = (const float*)d_in[2];  // (B,R,4C)
    const float* im_info   = (const float*)d_in[3];  // (B,3)
    const float* thr       = (const float*)d_in[4];  // (C,)
    float* out = (float*)d_out;

    const int R = in_sizes[0] / (BATCH * CNUM);      // 1000

    dim3 grid(NCLS, BATCH);
    fused_kernel<<<grid, 256>>>(cls_prob, rois, bbox_pred, im_info, thr,
                                out, out_size, R);
}

// round 5
// speedup vs baseline: 2.5467x; 1.2821x over previous
#include <cuda_runtime.h>
#include <math_constants.h>
#include <stdint.h>

#define BATCH   2
#define CNUM    81
#define NCLS    (CNUM - 1)
#define NP      CNUM
#define RMAX    1024
#define VMAX    256
#define NMS_THR 0.3f
#define NBLK    (NCLS * BATCH)   // 160

__device__ float g_dets[BATCH][NCLS][NP][5];
__device__ int   g_cnt[BATCH][NCLS];
__device__ unsigned int g_done = 0;

__global__ void __launch_bounds__(256)
fused_kernel(const float* __restrict__ cls_prob,   // (B,R,C)
             const float* __restrict__ rois,       // (B,R,5)
             const float* __restrict__ bbox_pred,  // (B,R,4C)
             const float* __restrict__ im_info,    // (B,3)
             const float* __restrict__ thr,        // (C,)
             float* __restrict__ out, int out_size,
             int R)
{
    const int c    = blockIdx.x + 1;
    const int b    = blockIdx.y;
    const int tid  = threadIdx.x;
    const int NT   = blockDim.x;
    const int lane = tid & 31;

    __shared__ unsigned long long ukey[RMAX];      // (inv_score)<<32 | roi_idx (compact)
    __shared__ float sx1[RMAX], sy1[RMAX], sx2[RMAX], sy2[RMAX], sar[RMAX];  // rank order
    __shared__ unsigned long long sup[VMAX][4];
    __shared__ unsigned char keep[RMAX];           // fallback only
    __shared__ int vcnt;

    if (tid == 0) vcnt = 0;
    __syncthreads();

    const float h_im = im_info[b * 3 + 0];
    const float w_im = im_info[b * 3 + 1];
    const float th   = thr[c];

    // ---- pass 1: score scan, warp-aggregated compaction ----
    for (int rr = tid; rr < RMAX; rr += NT) {
        float score = -1.0f;
        if (rr < R) score = cls_prob[(size_t)(b * R + rr) * CNUM + c];
        const bool valid = (rr < R) && (score > th);
        const unsigned mask = __ballot_sync(0xffffffffu, valid);
        if (mask) {
            const int leader = __ffs(mask) - 1;
            int base = 0;
            if (lane == leader) base = atomicAdd(&vcnt, __popc(mask));
            base = __shfl_sync(0xffffffffu, base, leader);
            if (valid) {
                const uint32_t ub = __float_as_uint(score) ^ 0x80000000u;
                const int pos = base + __popc(mask & ((1u << lane) - 1u));
                ukey[pos] = ((unsigned long long)(~ub) << 32) | (uint32_t)rr;
            }
        }
    }
    __syncthreads();

    const int V = vcnt;

    // ---- fused decode + rank + scatter (decode LDGs overlap rank compute) ----
    for (int p = tid; p < V; p += NT) {
        const unsigned long long kp = ukey[p];
        const int r = (int)(uint32_t)kp;

        // issue global loads early
        const float* roi = rois + (size_t)(b * R + r) * 5;
        const float x1 = roi[1], y1 = roi[2], x2 = roi[3], y2 = roi[4];
        const float4 d4 = *(const float4*)(bbox_pred + ((size_t)(b * R + r) * CNUM + c) * 4);

        // rank = #{smaller keys}; keys distinct (idx in low bits)
        int rank = 0;
        for (int j = 0; j < V; ++j)
            rank += (ukey[j] < kp);

        const float w  = x2 - x1 + 1.0f;
        const float h  = y2 - y1 + 1.0f;
        const float cx = x1 + 0.5f * w;
        const float cy = y1 + 0.5f * h;
        const float pcx = d4.x * 0.1f * w + cx;
        const float pcy = d4.y * 0.1f * h + cy;
        const float pw  = expf(d4.z * 0.2f) * w;
        const float ph  = expf(d4.w * 0.2f) * h;

        float nx1 = pcx - 0.5f * pw;
        float ny1 = pcy - 0.5f * ph;
        float nx2 = pcx + 0.5f * pw;
        float ny2 = pcy + 0.5f * ph;
        nx1 = fminf(fmaxf(nx1, 0.0f), w_im - 1.0f);
        nx2 = fminf(fmaxf(nx2, 0.0f), w_im - 1.0f);
        ny1 = fminf(fmaxf(ny1, 0.0f), h_im - 1.0f);
        ny2 = fminf(fmaxf(ny2, 0.0f), h_im - 1.0f);

        sx1[rank] = nx1; sy1[rank] = ny1; sx2[rank] = nx2; sy2[rank] = ny2;
        sar[rank] = fmaxf(nx2 - nx1, 0.0f) * fmaxf(ny2 - ny1, 0.0f);
    }
    __syncthreads();

    if (V <= VMAX) {
        const int W = (V + 63) >> 6;
        for (int t = tid; t < V * W; t += NT) {
            const int i = t / W;
            const int w = t - i * W;
            const float ax1 = sx1[i], ay1 = sy1[i];
            const float ax2 = sx2[i], ay2 = sy2[i];
            const float aa  = sar[i];
            unsigned long long bits = 0ULL;
            const int j0 = max(i + 1, w << 6);
            const int j1 = min(V, (w + 1) << 6);
            for (int j = j0; j < j1; ++j) {
                const float xx1 = fmaxf(ax1, sx1[j]);
                const float yy1 = fmaxf(ay1, sy1[j]);
                const float xx2 = fminf(ax2, sx2[j]);
                const float yy2 = fminf(ay2, sy2[j]);
                const float inter = fmaxf(xx2 - xx1, 0.0f) * fmaxf(yy2 - yy1, 0.0f);
                const float iou = inter / (aa + sar[j] - inter + 1e-9f);
                if (iou > NMS_THR) bits |= 1ULL << (j & 63);
            }
            sup[i][w] = bits;
        }
        __syncthreads();

        // ---- register-word greedy scan (no local-memory spills) ----
        if (tid == 0) {
            int k = 0;
            if (V <= 64) {
                unsigned long long rem =
                    (V >= 64) ? ~0ULL : ((1ULL << V) - 1ULL);
                while (rem) {
                    const int i = __ffsll((long long)rem) - 1;
                    rem &= ~(1ULL << i);
                    rem &= ~sup[i][0];
                    if (k < NP) {
                        g_dets[b][c - 1][k][0] = sx1[i];
                        g_dets[b][c - 1][k][1] = sy1[i];
                        g_dets[b][c - 1][k][2] = sx2[i];
                        g_dets[b][c - 1][k][3] = sy2[i];
                        g_dets[b][c - 1][k][4] = (float)c;
                    }
                    ++k;
                }
            } else {
                const int W2 = (V + 63) >> 6;
                auto wordinit = [&](int w) -> unsigned long long {
                    const int lo = w << 6;
                    if (V >= lo + 64) return ~0ULL;
                    if (V <= lo)      return 0ULL;
                    return (1ULL << (V - lo)) - 1ULL;
                };
                unsigned long long r0 = wordinit(0), r1 = wordinit(1);
                unsigned long long r2 = wordinit(2), r3 = wordinit(3);
                for (;;) {
                    int i;
                    if (r0)      { const int t = __ffsll((long long)r0) - 1; r0 &= ~(1ULL << t); i = t; }
                    else if (r1) { const int t = __ffsll((long long)r1) - 1; r1 &= ~(1ULL << t); i = 64 + t; }
                    else if (r2) { const int t = __ffsll((long long)r2) - 1; r2 &= ~(1ULL << t); i = 128 + t; }
                    else if (r3) { const int t = __ffsll((long long)r3) - 1; r3 &= ~(1ULL << t); i = 192 + t; }
                    else break;
                    r0 &= ~sup[i][0];
                    if (W2 > 1) r1 &= ~sup[i][1];
                    if (W2 > 2) r2 &= ~sup[i][2];
                    if (W2 > 3) r3 &= ~sup[i][3];
                    if (k < NP) {
                        g_dets[b][c - 1][k][0] = sx1[i];
                        g_dets[b][c - 1][k][1] = sy1[i];
                        g_dets[b][c - 1][k][2] = sx2[i];
                        g_dets[b][c - 1][k][3] = sy2[i];
                        g_dets[b][c - 1][k][4] = (float)c;
                    }
                    ++k;
                }
            }
            g_cnt[b][c - 1] = k;
        }
    } else {
        // ---- fallback: barrier-loop greedy NMS (rarely taken) ----
        for (int i = tid; i < V; i += NT) keep[i] = 1;
        __syncthreads();
        for (int i = 0; i < V; ++i) {
            if (keep[i]) {
                const float ax1 = sx1[i], ay1 = sy1[i];
                const float ax2 = sx2[i], ay2 = sy2[i];
                const float aa  = sar[i];
                for (int j = i + 1 + tid; j < V; j += NT) {
                    if (keep[j]) {
                        const float xx1 = fmaxf(ax1, sx1[j]);
                        const float yy1 = fmaxf(ay1, sy1[j]);
                        const float xx2 = fminf(ax2, sx2[j]);
                        const float yy2 = fminf(ay2, sy2[j]);
                        const float inter = fmaxf(xx2 - xx1, 0.0f) * fmaxf(yy2 - yy1, 0.0f);
                        const float iou = inter / (aa + sar[j] - inter + 1e-9f);
                        if (iou > NMS_THR) keep[j] = 0;
                    }
                }
            }
            __syncthreads();
        }
        if (tid == 0) {
            int k = 0;
            for (int i = 0; i < V; ++i) {
                if (keep[i]) {
                    if (k < NP) {
                        g_dets[b][c - 1][k][0] = sx1[i];
                        g_dets[b][c - 1][k][1] = sy1[i];
                        g_dets[b][c - 1][k][2] = sx2[i];
                        g_dets[b][c - 1][k][3] = sy2[i];
                        g_dets[b][c - 1][k][4] = (float)c;
                    }
                    ++k;
                }
            }
            g_cnt[b][c - 1] = k;
        }
    }

    // ======== last-block-done combine ========
    __threadfence();
    __syncthreads();

    __shared__ unsigned int is_last;
    if (tid == 0) is_last = (atomicAdd(&g_done, 1u) == NBLK - 1u) ? 1u : 0u;
    __syncthreads();
    if (!is_last) return;

    __shared__ int cnts[BATCH][NCLS];
    __shared__ int incl[BATCH][NCLS];

    for (int t = tid; t < BATCH * NCLS; t += NT) {
        const int bb = t / NCLS, cc = t - bb * NCLS;
        const int v = g_cnt[bb][cc];
        cnts[bb][cc] = v;
        incl[bb][cc] = v;
    }
    __syncthreads();

    // Hillis-Steele inclusive scan over the class axis (per image)
    for (int off = 1; off < NCLS; off <<= 1) {
        int add = 0;
        int bb = 0, cc = 0;
        const bool act = (tid < BATCH * NCLS);
        if (act) {
            bb = tid / NCLS; cc = tid - bb * NCLS;
            if (cc >= off) add = incl[bb][cc - off];
        }
        __syncthreads();
        if (act) incl[bb][cc] += add;
        __syncthreads();
    }

    // zero gt region
    for (int i = tid; i < BATCH * NP * 5; i += NT) out[i] = 0.0f;
    __syncthreads();

    for (int t = tid; t < BATCH * NP; t += NT) {
        const int bb = t / NP;
        const int k  = t - bb * NP;
        const int total = incl[bb][NCLS - 1];
        const int n = total < NP ? total : NP;
        if (k < n) {
            // binary search: first cc with incl[cc] > k
            int lo = 0, hi = NCLS - 1;
            while (lo < hi) {
                const int mid = (lo + hi) >> 1;
                if (incl[bb][mid] > k) hi = mid; else lo = mid + 1;
            }
            const int cc = lo;
            const int tt = k - (incl[bb][cc] - cnts[bb][cc]);
            float* gout = out + (size_t)bb * NP * 5 + (size_t)k * 5;
            #pragma unroll
            for (int q = 0; q < 5; ++q) gout[q] = g_dets[bb][cc][tt][q];
        }
        if (k == 0 && out_size >= BATCH * NP * 5 + BATCH)
            out[BATCH * NP * 5 + bb] = (float)n;
    }

    const int base = BATCH * NP * 5 + BATCH;
    for (int i = base + tid; i < out_size; i += NT) out[i] = 0.0f;

    __syncthreads();
    if (tid == 0) g_done = 0;   // reset for next graph replay
}

extern "C" void kernel_launch(void* const* d_in, const int* in_sizes, int n_in,
                              void* d_out, int out_size)
{
    const float* cls_prob  = (const float*)d_in[0];
    const float* rois      = (const float*)d_in[1];
    const float* bbox_pred = (const float*)d_in[2];
    const float* im_info   = (const float*)d_in[3];
    const float* thr       = (const float*)d_in[4];
    float* out = (float*)d_out;

    const int R = in_sizes[0] / (BATCH * CNUM);

    dim3 grid(NCLS, BATCH);
    fused_kernel<<<grid, 256>>>(cls_prob, rois, bbox_pred, im_info, thr,
                                out, out_size, R);
}